// round 9
// baseline (speedup 1.0000x reference)
#include <cuda_runtime.h>
#include <math.h>
#include <limits.h>

#define NB 128
#define NV 128000
#define N4 (NV/4)
#define NW (NV/16)        /* packed mask words per row (16 tokens/word) */
#define BPR 32
#define TPB 250           /* tiles (16 tokens) per block: NW/BPR */
#define CHUNK4 (N4/BPR)
#define TINYV 6.103515625e-05f
#define SEPS 1e-05f
#define CAP 8192
#define SCAP 256
#define SBUF 2048

__device__ unsigned g_pk[(size_t)NB*NW];   /* 2 bits/token: bit0 prompt, bit1 output */
__device__ int g_candcnt[NB];
__device__ float g_cand[NB*CAP];           /* EXACT candidate x values */
__device__ int g_cidx[NB*CAP];
__device__ float g_params[NB*8];

__device__ __forceinline__ unsigned ofl(float f){
  unsigned u = __float_as_uint(f);
  return (u & 0x80000000u) ? ~u : (u | 0x80000000u);
}
__device__ __forceinline__ float ifl(unsigned u){
  return __uint_as_float((u & 0x80000000u) ? (u & 0x7FFFFFFFu) : ~u);
}
/* EXACT mirror of reference arithmetic: l/pen (or l*pen), -pp, /temp */
__device__ __forceinline__ float xform(float l, unsigned mb, float rp, float pp, float tv){
  float x = l;
  if (mb){
    x = (l > 0.f) ? __fdiv_rn(l, rp) : __fmul_rn(l, rp);
    if (mb & 2u) x = __fsub_rn(x, pp);
  }
  return __fdiv_rn(x, tv);
}
/* FAST penalized logit (y-space: no temperature; selection order is tv-invariant) */
__device__ __forceinline__ float yfast(float l, unsigned mb, float rp, float rrp, float pp){
  float y = l;
  if (mb){
    y = (l > 0.f) ? l*rrp : l*rp;
    if (mb & 2u) y -= pp;
  }
  return y;
}

__global__ void k_init(){
  size_t i0 = (size_t)blockIdx.x*blockDim.x + threadIdx.x;
  size_t n = (size_t)NB*NW;
  for (size_t i = i0; i < n; i += (size_t)gridDim.x*blockDim.x) g_pk[i] = 0u;
  if (i0 < NB) g_candcnt[i0] = 0;
}

__global__ void k_scatter(const int* __restrict__ toks, int L, unsigned bit){
  int i = blockIdx.x*blockDim.x + threadIdx.x;
  if (i >= NB*L) return;
  int row = i / L;
  int t = toks[i];
  if (t >= 0 && t < NV)
    atomicOr(&g_pk[(size_t)row*NW + (t >> 4)], bit << ((t & 15)*2));
}

/* fused: chunk y-max, mask output emission, superset candidate collection */
__global__ __launch_bounds__(256) void k_pass1(
  const float* __restrict__ logits, const float* __restrict__ presence,
  const float* __restrict__ rep, const float* __restrict__ temp,
  float* __restrict__ out, int mode)
{
  __shared__ float s_red[8];
  __shared__ float s_bmax;
  __shared__ float sb_v[SBUF];
  __shared__ int   sb_i[SBUF];
  __shared__ unsigned sb_n;
  __shared__ unsigned sb_base;

  int row = blockIdx.y;
  int tid = threadIdx.x;
  float rp = rep[row], pp = presence[row];
  float tv = temp[row]; if (tv < SEPS) tv = 1.f;
  float rrp = __fdividef(1.f, rp);
  int baseT = blockIdx.x*TPB;                 /* tile = 16 tokens = 1 pk word */
  const unsigned* pkrow = g_pk + (size_t)row*NW;
  const float4* l4 = (const float4*)(logits + (size_t)row*NV);

  if (tid == 0) sb_n = 0;

  float ym = -INFINITY;
  if (tid < TPB){
    int t = baseT + tid;
    unsigned w = pkrow[t];
    float4 A = l4[t*4+0], B = l4[t*4+1], C = l4[t*4+2], D = l4[t*4+3];
    if (w == 0u){
      float m0 = fmaxf(fmaxf(A.x,A.y), fmaxf(A.z,A.w));
      float m1 = fmaxf(fmaxf(B.x,B.y), fmaxf(B.z,B.w));
      float m2 = fmaxf(fmaxf(C.x,C.y), fmaxf(C.z,C.w));
      float m3 = fmaxf(fmaxf(D.x,D.y), fmaxf(D.z,D.w));
      ym = fmaxf(fmaxf(m0,m1), fmaxf(m2,m3));
    } else {
      const float* lv = &A.x;  /* A..D contiguous in regs via array trick below */
      float buf[16] = {A.x,A.y,A.z,A.w,B.x,B.y,B.z,B.w,C.x,C.y,C.z,C.w,D.x,D.y,D.z,D.w};
      #pragma unroll
      for (int k = 0; k < 16; k++)
        ym = fmaxf(ym, yfast(buf[k], (w >> (2*k)) & 3u, rp, rrp, pp));
      (void)lv;
    }
    /* emit mask outputs (no extra pass over logits) */
    if (mode == 1){
      float4* pm4 = ((float4*)(out + (size_t)NB*NV + (size_t)row*NV)) + t*4;
      float4* om4 = ((float4*)(out + 2*(size_t)NB*NV + (size_t)row*NV)) + t*4;
      #pragma unroll
      for (int q = 0; q < 4; q++){
        unsigned b8 = w >> (8*q);
        float4 pm, om;
        pm.x = (b8 & 0x01u) ? 1.f : 0.f;  om.x = (b8 & 0x02u) ? 1.f : 0.f;
        pm.y = (b8 & 0x04u) ? 1.f : 0.f;  om.y = (b8 & 0x08u) ? 1.f : 0.f;
        pm.z = (b8 & 0x10u) ? 1.f : 0.f;  om.z = (b8 & 0x20u) ? 1.f : 0.f;
        pm.w = (b8 & 0x40u) ? 1.f : 0.f;  om.w = (b8 & 0x80u) ? 1.f : 0.f;
        pm4[q] = pm; om4[q] = om;
      }
    } else if (mode == 2){
      unsigned char* bp = (unsigned char*)out + (size_t)NB*NV*4;
      uchar4* pm4 = ((uchar4*)(bp + (size_t)row*NV)) + t*4;
      uchar4* om4 = ((uchar4*)(bp + (size_t)NB*NV + (size_t)row*NV)) + t*4;
      #pragma unroll
      for (int q = 0; q < 4; q++){
        unsigned b8 = w >> (8*q);
        uchar4 pm, om;
        pm.x = (b8 & 0x01u) ? 1 : 0;  om.x = (b8 & 0x02u) ? 1 : 0;
        pm.y = (b8 & 0x04u) ? 1 : 0;  om.y = (b8 & 0x08u) ? 1 : 0;
        pm.z = (b8 & 0x10u) ? 1 : 0;  om.z = (b8 & 0x20u) ? 1 : 0;
        pm.w = (b8 & 0x40u) ? 1 : 0;  om.w = (b8 & 0x80u) ? 1 : 0;
        pm4[q] = pm; om4[q] = om;
      }
    }
  }
  #pragma unroll
  for (int o = 16; o > 0; o >>= 1) ym = fmaxf(ym, __shfl_xor_sync(0xFFFFFFFFu, ym, o));
  if ((tid & 31) == 0) s_red[tid >> 5] = ym;
  __syncthreads();
  if (tid == 0){
    float v = s_red[0];
    #pragma unroll
    for (int w2 = 1; w2 < 8; w2++) v = fmaxf(v, s_red[w2]);
    s_bmax = v;
  }
  __syncthreads();
  float cut = s_bmax - 0.38f*fabsf(s_bmax) - 0.52f;  /* y-space superset cut */

  if (tid < TPB){
    int t = baseT + tid;
    unsigned w = pkrow[t];
    float4 A = l4[t*4+0], B = l4[t*4+1], C = l4[t*4+2], D = l4[t*4+3];  /* L1 hits */
    float buf[16] = {A.x,A.y,A.z,A.w,B.x,B.y,B.z,B.w,C.x,C.y,C.z,C.w,D.x,D.y,D.z,D.w};
    if (w == 0u){
      #pragma unroll
      for (int k = 0; k < 16; k++){
        if (buf[k] >= cut){
          float ex = __fdiv_rn(buf[k], tv);        /* exact x, rare */
          unsigned id = atomicAdd(&sb_n, 1u);
          if (id < SBUF){ sb_v[id] = ex; sb_i[id] = t*16 + k; }
          else {
            int p = atomicAdd(&g_candcnt[row], 1);
            if (p < CAP){ g_cand[row*CAP + p] = ex; g_cidx[row*CAP + p] = t*16 + k; }
          }
        }
      }
    } else {
      #pragma unroll
      for (int k = 0; k < 16; k++){
        unsigned mb = (w >> (2*k)) & 3u;
        float y = yfast(buf[k], mb, rp, rrp, pp);
        if (y >= cut){
          float ex = xform(buf[k], mb, rp, pp, tv);  /* exact x, rare */
          unsigned id = atomicAdd(&sb_n, 1u);
          if (id < SBUF){ sb_v[id] = ex; sb_i[id] = t*16 + k; }
          else {
            int p = atomicAdd(&g_candcnt[row], 1);
            if (p < CAP){ g_cand[row*CAP + p] = ex; g_cidx[row*CAP + p] = t*16 + k; }
          }
        }
      }
    }
  }
  __syncthreads();
  unsigned n = sb_n; if (n > SBUF) n = SBUF;
  if (tid == 0) sb_base = (unsigned)atomicAdd(&g_candcnt[row], (int)n);
  __syncthreads();
  unsigned b0 = sb_base;
  for (unsigned i = tid; i < n; i += 256){
    unsigned p = b0 + i;
    if (p < CAP){ g_cand[row*CAP + p] = sb_v[i]; g_cidx[row*CAP + p] = sb_i[i]; }
  }
}

__global__ __launch_bounds__(256) void k_select(
  const float* __restrict__ logits, const float* __restrict__ presence,
  const float* __restrict__ rep, const float* __restrict__ temp,
  const int* __restrict__ topk, const float* __restrict__ topp)
{
  __shared__ unsigned s_hist[256];
  __shared__ float s_small[SCAP];
  __shared__ float s_e[SCAP];
  __shared__ double s_d[SCAP];
  __shared__ unsigned s_cnt;
  __shared__ unsigned s_maxu;
  __shared__ int s_sel, s_want, s_jstar;

  int row = blockIdx.x, tid = threadIdx.x;
  int kneed = topk[row]; if (kneed < 1) kneed = 1; if (kneed > NV) kneed = NV;
  float tp = topp[row];
  int count = g_candcnt[row];
  float* cand = g_cand + row*CAP;
  int* cidx = g_cidx + row*CAP;

  /* exact row max from exact candidates */
  if (tid == 0) s_maxu = 0u;
  __syncthreads();
  {
    int c0 = count > CAP ? CAP : count;
    float lm = -INFINITY;
    for (int i = tid; i < c0; i += 256) lm = fmaxf(lm, cand[i]);
    #pragma unroll
    for (int o = 16; o > 0; o >>= 1) lm = fmaxf(lm, __shfl_xor_sync(0xFFFFFFFFu, lm, o));
    if ((tid & 31) == 0) atomicMax(&s_maxu, ofl(lm));
  }
  __syncthreads();
  float M = ifl(s_maxu);

  if (!(count >= kneed && count <= CAP)){
    /* fallback: bracketed exact search (cold path) */
    float rp = rep[row], pp = presence[row];
    float tv = temp[row]; if (tv < SEPS) tv = 1.f;
    const float4* l4 = (const float4*)(logits + (size_t)row*NV);
    const unsigned* pkrow = g_pk + (size_t)row*NW;
    float delta = 0.38f*fabsf(M) + 0.5f;
    float dlo = 0.f, dhi = -1.f;
    if (count < kneed){ dlo = delta; delta *= 2.f; }
    else              { dhi = delta; delta *= 0.5f; }
    for (int it = 0; it < 64; it++){
      float c2 = M - delta;
      if (tid == 0) s_cnt = 0;
      __syncthreads();
      for (int i = tid; i < N4; i += 256){
        float4 l = l4[i];
        unsigned w = pkrow[i >> 2];
        unsigned m8 = (w >> ((i & 3) << 3)) & 0xFFu;
        float v[4];
        v[0] = xform(l.x, (m8     )&3u, rp, pp, tv);
        v[1] = xform(l.y, (m8 >> 2)&3u, rp, pp, tv);
        v[2] = xform(l.z, (m8 >> 4)&3u, rp, pp, tv);
        v[3] = xform(l.w, (m8 >> 6)&3u, rp, pp, tv);
        #pragma unroll
        for (int j = 0; j < 4; j++){
          if (v[j] >= c2){
            unsigned id = atomicAdd(&s_cnt, 1u);
            if (id < CAP){ cand[id] = v[j]; cidx[id] = i*4 + j; }
          }
        }
      }
      __syncthreads();
      count = (int)s_cnt;
      __syncthreads();
      if (count >= kneed && count <= CAP) break;
      if (count < kneed){ dlo = delta; delta = (dhi > 0.f) ? 0.5f*(delta + dhi) : delta*2.f; }
      else              { dhi = delta; delta = 0.5f*(dlo + delta); }
    }
    if (count > CAP) count = CAP;
    if (count < kneed) kneed = count;
    if (tid == 0) s_maxu = 0u;
    __syncthreads();
    float lm = -INFINITY;
    for (int i = tid; i < count; i += 256) lm = fmaxf(lm, cand[i]);
    #pragma unroll
    for (int o = 16; o > 0; o >>= 1) lm = fmaxf(lm, __shfl_xor_sync(0xFFFFFFFFu, lm, o));
    if ((tid & 31) == 0) atomicMax(&s_maxu, ofl(lm));
    __syncthreads();
    M = ifl(s_maxu);
  }
  __syncthreads();
  if (tid == 0) g_candcnt[row] = count;   /* publish final count for k_spray */

  /* radix-select k-th largest value */
  unsigned prefix = 0; int want = kneed;
  for (int shift = 24; shift >= 0; shift -= 8){
    s_hist[tid] = 0;
    __syncthreads();
    unsigned himask = (shift == 24) ? 0u : (0xFFFFFFFFu << (shift + 8));
    for (int i = tid; i < count; i += 256){
      unsigned ou = ofl(cand[i]);
      if ((ou & himask) == prefix) atomicAdd(&s_hist[(ou >> shift) & 255u], 1u);
    }
    __syncthreads();
    if (tid == 0){
      int c = 0, b = 255;
      for (; b > 0; b--){
        int h = (int)s_hist[b];
        if (c + h >= want) break;
        c += h;
      }
      s_sel = b; s_want = want - c;
    }
    __syncthreads();
    prefix |= ((unsigned)s_sel) << shift;
    want = s_want;
    __syncthreads();
  }
  float thr = ifl(prefix);

  /* gather survivors >= thr */
  if (tid == 0) s_cnt = 0;
  __syncthreads();
  for (int i = tid; i < count; i += 256){
    float v = cand[i];
    if (v >= thr){
      unsigned id = atomicAdd(&s_cnt, 1u);
      if (id < SCAP) s_small[id] = v;
    }
  }
  __syncthreads();
  int m = (int)s_cnt; if (m > SCAP) m = SCAP;
  if (tid >= m) s_small[tid] = -INFINITY;
  __syncthreads();

  /* bitonic sort descending */
  for (int k = 2; k <= SCAP; k <<= 1){
    for (int j = k >> 1; j > 0; j >>= 1){
      int ixj = tid ^ j;
      if (ixj > tid){
        float a = s_small[tid], b = s_small[ixj];
        bool desc = ((tid & k) == 0);
        if (desc ? (a < b) : (a > b)){ s_small[tid] = b; s_small[ixj] = a; }
      }
      __syncthreads();
    }
  }
  float ex_tiny = expf(__fsub_rn(TINYV, M));
  s_e[tid] = (tid < m) ? expf(s_small[tid] - M) : 0.f;
  __syncthreads();

  /* parallel suffix sums */
  s_d[tid] = (double)s_e[tid];
  __syncthreads();
  #pragma unroll
  for (int off = 1; off < SCAP; off <<= 1){
    double add = (tid + off < SCAP) ? s_d[tid + off] : 0.0;
    __syncthreads();
    s_d[tid] += add;
    __syncthreads();
  }
  double T = (double)(NV - m) * (double)ex_tiny;
  double Z1 = T + s_d[0];
  double need = (double)__fsub_rn(1.0f, tp) * Z1;
  if (tid == 0) s_jstar = 0;
  __syncthreads();
  if (tid < m && (T + s_d[tid]) > need) atomicMax(&s_jstar, tid);
  __syncthreads();

  if (tid == 0){
    int jstar = s_jstar;
    float thrf = s_small[jstar];
    int nsel = jstar + 1;

    /* tie handling at top-p boundary (stable argsort keeps larger token idx) */
    int lo = jstar;
    while (lo > 0 && s_small[lo-1] == thrf) lo--;
    int q = jstar - lo + 1;
    int dcnt = 0;
    for (int i = jstar; i < m && s_small[i] == thrf; i++) dcnt++;
    dcnt += q - 1;
    int idx_cut = INT_MIN;
    if (q < dcnt){
      int idxs[64]; int dt = 0;
      for (int i = 0; i < count && dt < 64; i++)
        if (cand[i] == thrf) idxs[dt++] = cidx[i];
      if (q < dt){
        for (int a = 0; a < q; a++){
          int best = a;
          for (int b2 = a+1; b2 < dt; b2++) if (idxs[b2] > idxs[best]) best = b2;
          int t2 = idxs[a]; idxs[a] = idxs[best]; idxs[best] = t2;
        }
        idx_cut = idxs[q-1];
      }
    }

    double Zsel = s_d[0] - ((jstar+1 < SCAP) ? s_d[jstar+1] : 0.0);
    double Z2 = (double)(NV - nsel) * (double)ex_tiny + Zsel;
    float Z2f = (float)Z2;
    float invZ2 = 1.0f / Z2f;
    g_params[row*8+0] = thrf;
    g_params[row*8+1] = M;
    g_params[row*8+2] = invZ2;
    g_params[row*8+3] = __fdiv_rn(ex_tiny, Z2f);
    g_params[row*8+4] = __int_as_float(idx_cut);
  }
}

/* pure-write splat of per-row tiny prob */
__global__ __launch_bounds__(256) void k_fillprobs(float* __restrict__ out){
  int row = blockIdx.y;
  float tinyP = g_params[row*8+3];
  float4 f = make_float4(tinyP, tinyP, tinyP, tinyP);
  float4* o4 = ((float4*)(out + (size_t)row*NV)) + blockIdx.x*CHUNK4;
  for (int i = threadIdx.x; i < CHUNK4; i += 256) o4[i] = f;
}

/* sparse survivor writes (runs after fill) */
__global__ __launch_bounds__(256) void k_spray(float* __restrict__ out){
  int row = blockIdx.x;
  float thrf = g_params[row*8+0], M = g_params[row*8+1], invZ2 = g_params[row*8+2];
  int idx_cut = __float_as_int(g_params[row*8+4]);
  int count = g_candcnt[row]; if (count > CAP) count = CAP;
  const float* cand = g_cand + row*CAP;
  const int* cidx = g_cidx + row*CAP;
  for (int i = threadIdx.x; i < count; i += 256){
    float v = cand[i];
    int gi = cidx[i];
    if ((v > thrf) || (v == thrf && gi >= idx_cut))
      out[(size_t)row*NV + gi] = expf(v - M) * invZ2;
  }
}

extern "C" void kernel_launch(void* const* d_in, const int* in_sizes, int n_in,
                              void* d_out, int out_size) {
  /* size-based input resolution (robust to dict vs alphabetical metadata order) */
  int il = -1, t0 = -1, t1 = -1;
  for (int i = 0; i < n_in; i++){
    if (in_sizes[i] == NB*NV && il < 0) il = i;
    else if (in_sizes[i] > NB){ if (t0 < 0) t0 = i; else t1 = i; }
  }
  int ip, io;
  if (in_sizes[t0] >= in_sizes[t1]){ ip = t0; io = t1; } else { ip = t1; io = t0; }
  int s[6], ns = 0;
  for (int i = 0; i < n_in; i++)
    if (i != il && i != ip && i != io && ns < 6) s[ns++] = i;
  int ipres = (ip < io) ? s[0] : s[1];
  int irep = s[2], itemp = s[3], itopk = s[4], itopp = s[5];

  const float* logits = (const float*)d_in[il];
  const int*   ptoks  = (const int*)d_in[ip];
  const int*   otoks  = (const int*)d_in[io];
  const float* pres   = (const float*)d_in[ipres];
  const float* rep    = (const float*)d_in[irep];
  const float* temp   = (const float*)d_in[itemp];
  const int*   tk     = (const int*)d_in[itopk];
  const float* tp     = (const float*)d_in[itopp];
  float* out = (float*)d_out;

  int PL = in_sizes[ip] / NB;
  int OL = in_sizes[io] / NB;

  long long bv = (long long)NB * NV;
  int mode = 0;
  if ((long long)out_size >= 3*bv) mode = 1;                 /* masks as float */
  else if ((long long)out_size >= bv + bv/2) mode = 2;       /* masks as bytes */

  k_init<<<512, 256>>>();
  k_scatter<<<(NB*PL + 255)/256, 256>>>(ptoks, PL, 1u);
  k_scatter<<<(NB*OL + 255)/256, 256>>>(otoks, OL, 2u);
  dim3 grid(BPR, NB);
  k_pass1<<<grid, 256>>>(logits, pres, rep, temp, out, mode);
  k_select<<<NB, 256>>>(logits, pres, rep, temp, tk, tp);
  k_fillprobs<<<grid, 256>>>(out);
  k_spray<<<NB, 256>>>(out);
}

// round 10
// speedup vs baseline: 1.1199x; 1.1199x over previous
#include <cuda_runtime.h>
#include <math.h>
#include <limits.h>

#define NB 128
#define NV 128000
#define N4 (NV/4)
#define NW (NV/16)        /* packed mask words per row (16 tokens/word) */
#define BPR 32
#define CHUNK4 (N4/BPR)   /* 1000 float4 per block */
#define TINYV 6.103515625e-05f
#define SEPS 1e-05f
#define CAP 8192
#define SCAP 256
#define SBUF 2048
#define CUTMARG 0.02f

__device__ unsigned g_pk[(size_t)NB*NW];   /* 2 bits/token: bit0 prompt, bit1 output */
__device__ int g_candcnt[NB];
__device__ float g_cand[NB*CAP];           /* EXACT candidate x values */
__device__ int g_cidx[NB*CAP];
__device__ float g_params[NB*8];

__device__ __forceinline__ unsigned ofl(float f){
  unsigned u = __float_as_uint(f);
  return (u & 0x80000000u) ? ~u : (u | 0x80000000u);
}
__device__ __forceinline__ float ifl(unsigned u){
  return __uint_as_float((u & 0x80000000u) ? (u & 0x7FFFFFFFu) : ~u);
}
__device__ __forceinline__ float cutf(float M){
  return M - 0.38f*fabsf(M) - 0.5f;
}
/* EXACT mirror of reference arithmetic: l/pen (or l*pen), -pp, /temp */
__device__ __forceinline__ float xform(float l, unsigned mb, float rp, float pp, float tv){
  float x = l;
  if (mb){
    x = (l > 0.f) ? __fdiv_rn(l, rp) : __fmul_rn(l, rp);
    if (mb & 2u) x = __fsub_rn(x, pp);
  }
  return __fdiv_rn(x, tv);
}
/* FAST approx for comparisons: |err| <= ~2e-6*|x| + 2e-5 */
__device__ __forceinline__ float xfast(float l, unsigned mb, float rp, float rrp,
                                       float pp, float rtv){
  float x = l;
  if (mb){
    x = (l > 0.f) ? l*rrp : l*rp;
    if (mb & 2u) x -= pp;
  }
  return x * rtv;
}
__device__ __forceinline__ unsigned mask8(const unsigned* __restrict__ pk, int i){
  unsigned w = pk[i >> 2];
  return (w >> ((i & 3) << 3)) & 0xFFu;
}

__global__ void k_init(){
  size_t i0 = (size_t)blockIdx.x*blockDim.x + threadIdx.x;
  size_t n = (size_t)NB*NW;
  for (size_t i = i0; i < n; i += (size_t)gridDim.x*blockDim.x) g_pk[i] = 0u;
  if (i0 < NB) g_candcnt[i0] = 0;
}

__global__ void k_scatter(const int* __restrict__ toks, int L, unsigned bit){
  int i = blockIdx.x*blockDim.x + threadIdx.x;
  if (i >= NB*L) return;
  int row = i / L;
  int t = toks[i];
  if (t >= 0 && t < NV)
    atomicOr(&g_pk[(size_t)row*NW + (t >> 4)], bit << ((t & 15)*2));
}

/* R8-proven structure: fused chunk-max + superset candidate collection (reads only) */
__global__ __launch_bounds__(256) void k_pass1(
  const float* __restrict__ logits, const float* __restrict__ presence,
  const float* __restrict__ rep, const float* __restrict__ temp)
{
  __shared__ float s_red[8];
  __shared__ float s_bmax;
  __shared__ float sb_v[SBUF];
  __shared__ int   sb_i[SBUF];
  __shared__ unsigned sb_n;
  __shared__ unsigned sb_base;

  int row = blockIdx.y;
  float rp = rep[row], pp = presence[row];
  float tv = temp[row]; if (tv < SEPS) tv = 1.f;
  float rrp = __fdividef(1.f, rp), rtv = __fdividef(1.f, tv);
  int base = blockIdx.x*CHUNK4;
  const float4* l4 = ((const float4*)(logits + (size_t)row*NV)) + base;
  const unsigned* pkrow = g_pk + (size_t)row*NW;

  if (threadIdx.x == 0) sb_n = 0;

  float mymax = -INFINITY;
  for (int i = threadIdx.x; i < CHUNK4; i += 256){
    float4 l = l4[i];
    unsigned m8 = mask8(pkrow, base + i);
    float a = xfast(l.x, (m8     )&3u, rp, rrp, pp, rtv);
    float b = xfast(l.y, (m8 >> 2)&3u, rp, rrp, pp, rtv);
    float c = xfast(l.z, (m8 >> 4)&3u, rp, rrp, pp, rtv);
    float d = xfast(l.w, (m8 >> 6)&3u, rp, rrp, pp, rtv);
    mymax = fmaxf(fmaxf(mymax, fmaxf(a, b)), fmaxf(c, d));
  }
  #pragma unroll
  for (int o = 16; o > 0; o >>= 1) mymax = fmaxf(mymax, __shfl_xor_sync(0xFFFFFFFFu, mymax, o));
  if ((threadIdx.x & 31) == 0) s_red[threadIdx.x >> 5] = mymax;
  __syncthreads();
  if (threadIdx.x == 0){
    float v = s_red[0];
    #pragma unroll
    for (int w = 1; w < 8; w++) v = fmaxf(v, s_red[w]);
    s_bmax = v;
  }
  __syncthreads();
  float cut = cutf(s_bmax) - CUTMARG;   /* margin covers approx error */

  for (int i = threadIdx.x; i < CHUNK4; i += 256){
    float4 l = l4[i];                                   /* L1/L2 hit */
    unsigned m8 = mask8(pkrow, base + i);
    float v[4];
    v[0] = xfast(l.x, (m8     )&3u, rp, rrp, pp, rtv);
    v[1] = xfast(l.y, (m8 >> 2)&3u, rp, rrp, pp, rtv);
    v[2] = xfast(l.z, (m8 >> 4)&3u, rp, rrp, pp, rtv);
    v[3] = xfast(l.w, (m8 >> 6)&3u, rp, rrp, pp, rtv);
    float lv[4] = {l.x, l.y, l.z, l.w};
    #pragma unroll
    for (int j = 0; j < 4; j++){
      if (v[j] >= cut){
        float ex = xform(lv[j], (m8 >> (2*j))&3u, rp, pp, tv);  /* EXACT, rare */
        unsigned id = atomicAdd(&sb_n, 1u);
        if (id < SBUF){ sb_v[id] = ex; sb_i[id] = (base + i)*4 + j; }
        else {
          int p = atomicAdd(&g_candcnt[row], 1);
          if (p < CAP){ g_cand[row*CAP + p] = ex; g_cidx[row*CAP + p] = (base + i)*4 + j; }
        }
      }
    }
  }
  __syncthreads();
  unsigned n = sb_n; if (n > SBUF) n = SBUF;
  if (threadIdx.x == 0) sb_base = (unsigned)atomicAdd(&g_candcnt[row], (int)n);
  __syncthreads();
  unsigned b0 = sb_base;
  for (unsigned i = threadIdx.x; i < n; i += 256){
    unsigned p = b0 + i;
    if (p < CAP){ g_cand[row*CAP + p] = sb_v[i]; g_cidx[row*CAP + p] = sb_i[i]; }
  }
}

__global__ __launch_bounds__(256) void k_select(
  const float* __restrict__ logits, const float* __restrict__ presence,
  const float* __restrict__ rep, const float* __restrict__ temp,
  const int* __restrict__ topk, const float* __restrict__ topp)
{
  __shared__ unsigned s_hist[256];
  __shared__ float s_small[SCAP];
  __shared__ float s_e[SCAP];
  __shared__ double s_d[SCAP];
  __shared__ unsigned s_cnt;
  __shared__ unsigned s_maxu;
  __shared__ int s_sel, s_want, s_jstar;

  int row = blockIdx.x, tid = threadIdx.x;
  int kneed = topk[row]; if (kneed < 1) kneed = 1; if (kneed > NV) kneed = NV;
  float tp = topp[row];
  int count = g_candcnt[row];
  float* cand = g_cand + row*CAP;
  int* cidx = g_cidx + row*CAP;

  /* exact row max from exact candidates */
  if (tid == 0) s_maxu = 0u;
  __syncthreads();
  {
    int c0 = count > CAP ? CAP : count;
    float lm = -INFINITY;
    for (int i = tid; i < c0; i += 256) lm = fmaxf(lm, cand[i]);
    #pragma unroll
    for (int o = 16; o > 0; o >>= 1) lm = fmaxf(lm, __shfl_xor_sync(0xFFFFFFFFu, lm, o));
    if ((tid & 31) == 0) atomicMax(&s_maxu, ofl(lm));
  }
  __syncthreads();
  float M = ifl(s_maxu);

  if (!(count >= kneed && count <= CAP)){
    /* fallback: bracketed exact search (cold path) */
    float rp = rep[row], pp = presence[row];
    float tv = temp[row]; if (tv < SEPS) tv = 1.f;
    const float4* l4 = (const float4*)(logits + (size_t)row*NV);
    const unsigned* pkrow = g_pk + (size_t)row*NW;
    float delta = 0.38f*fabsf(M) + 0.5f;
    float dlo = 0.f, dhi = -1.f;
    if (count < kneed){ dlo = delta; delta *= 2.f; }
    else              { dhi = delta; delta *= 0.5f; }
    for (int it = 0; it < 64; it++){
      float c2 = M - delta;
      if (tid == 0) s_cnt = 0;
      __syncthreads();
      for (int i = tid; i < N4; i += 256){
        float4 l = l4[i];
        unsigned m8 = mask8(pkrow, i);
        float v[4];
        v[0] = xform(l.x, (m8     )&3u, rp, pp, tv);
        v[1] = xform(l.y, (m8 >> 2)&3u, rp, pp, tv);
        v[2] = xform(l.z, (m8 >> 4)&3u, rp, pp, tv);
        v[3] = xform(l.w, (m8 >> 6)&3u, rp, pp, tv);
        #pragma unroll
        for (int j = 0; j < 4; j++){
          if (v[j] >= c2){
            unsigned id = atomicAdd(&s_cnt, 1u);
            if (id < CAP){ cand[id] = v[j]; cidx[id] = i*4 + j; }
          }
        }
      }
      __syncthreads();
      count = (int)s_cnt;
      __syncthreads();
      if (count >= kneed && count <= CAP) break;
      if (count < kneed){ dlo = delta; delta = (dhi > 0.f) ? 0.5f*(delta + dhi) : delta*2.f; }
      else              { dhi = delta; delta = 0.5f*(dlo + delta); }
    }
    if (count > CAP) count = CAP;
    if (count < kneed) kneed = count;
    if (tid == 0) s_maxu = 0u;
    __syncthreads();
    float lm = -INFINITY;
    for (int i = tid; i < count; i += 256) lm = fmaxf(lm, cand[i]);
    #pragma unroll
    for (int o = 16; o > 0; o >>= 1) lm = fmaxf(lm, __shfl_xor_sync(0xFFFFFFFFu, lm, o));
    if ((tid & 31) == 0) atomicMax(&s_maxu, ofl(lm));
    __syncthreads();
    M = ifl(s_maxu);
  }
  __syncthreads();
  if (tid == 0) g_candcnt[row] = count;   /* publish final count for k_spray */

  /* radix-select k-th largest value */
  unsigned prefix = 0; int want = kneed;
  for (int shift = 24; shift >= 0; shift -= 8){
    s_hist[tid] = 0;
    __syncthreads();
    unsigned himask = (shift == 24) ? 0u : (0xFFFFFFFFu << (shift + 8));
    for (int i = tid; i < count; i += 256){
      unsigned ou = ofl(cand[i]);
      if ((ou & himask) == prefix) atomicAdd(&s_hist[(ou >> shift) & 255u], 1u);
    }
    __syncthreads();
    if (tid == 0){
      int c = 0, b = 255;
      for (; b > 0; b--){
        int h = (int)s_hist[b];
        if (c + h >= want) break;
        c += h;
      }
      s_sel = b; s_want = want - c;
    }
    __syncthreads();
    prefix |= ((unsigned)s_sel) << shift;
    want = s_want;
    __syncthreads();
  }
  float thr = ifl(prefix);

  /* gather survivors >= thr */
  if (tid == 0) s_cnt = 0;
  __syncthreads();
  for (int i = tid; i < count; i += 256){
    float v = cand[i];
    if (v >= thr){
      unsigned id = atomicAdd(&s_cnt, 1u);
      if (id < SCAP) s_small[id] = v;
    }
  }
  __syncthreads();
  int m = (int)s_cnt; if (m > SCAP) m = SCAP;
  if (tid >= m) s_small[tid] = -INFINITY;
  __syncthreads();

  /* bitonic sort descending */
  for (int k = 2; k <= SCAP; k <<= 1){
    for (int j = k >> 1; j > 0; j >>= 1){
      int ixj = tid ^ j;
      if (ixj > tid){
        float a = s_small[tid], b = s_small[ixj];
        bool desc = ((tid & k) == 0);
        if (desc ? (a < b) : (a > b)){ s_small[tid] = b; s_small[ixj] = a; }
      }
      __syncthreads();
    }
  }
  float ex_tiny = expf(__fsub_rn(TINYV, M));
  s_e[tid] = (tid < m) ? expf(s_small[tid] - M) : 0.f;
  __syncthreads();

  /* parallel suffix sums */
  s_d[tid] = (double)s_e[tid];
  __syncthreads();
  #pragma unroll
  for (int off = 1; off < SCAP; off <<= 1){
    double add = (tid + off < SCAP) ? s_d[tid + off] : 0.0;
    __syncthreads();
    s_d[tid] += add;
    __syncthreads();
  }
  double T = (double)(NV - m) * (double)ex_tiny;
  double Z1 = T + s_d[0];
  double need = (double)__fsub_rn(1.0f, tp) * Z1;
  if (tid == 0) s_jstar = 0;
  __syncthreads();
  if (tid < m && (T + s_d[tid]) > need) atomicMax(&s_jstar, tid);
  __syncthreads();

  if (tid == 0){
    int jstar = s_jstar;
    float thrf = s_small[jstar];
    int nsel = jstar + 1;

    /* tie handling at top-p boundary (stable argsort keeps larger token idx) */
    int lo = jstar;
    while (lo > 0 && s_small[lo-1] == thrf) lo--;
    int q = jstar - lo + 1;
    int dcnt = 0;
    for (int i = jstar; i < m && s_small[i] == thrf; i++) dcnt++;
    dcnt += q - 1;
    int idx_cut = INT_MIN;
    if (q < dcnt){
      int idxs[64]; int dt = 0;
      for (int i = 0; i < count && dt < 64; i++)
        if (cand[i] == thrf) idxs[dt++] = cidx[i];
      if (q < dt){
        for (int a = 0; a < q; a++){
          int best = a;
          for (int b2 = a+1; b2 < dt; b2++) if (idxs[b2] > idxs[best]) best = b2;
          int t2 = idxs[a]; idxs[a] = idxs[best]; idxs[best] = t2;
        }
        idx_cut = idxs[q-1];
      }
    }

    double Zsel = s_d[0] - ((jstar+1 < SCAP) ? s_d[jstar+1] : 0.0);
    double Z2 = (double)(NV - nsel) * (double)ex_tiny + Zsel;
    float Z2f = (float)Z2;
    float invZ2 = 1.0f / Z2f;
    g_params[row*8+0] = thrf;
    g_params[row*8+1] = M;
    g_params[row*8+2] = invZ2;
    g_params[row*8+3] = __fdiv_rn(ex_tiny, Z2f);
    g_params[row*8+4] = __int_as_float(idx_cut);
  }
}

/* pure streaming writes: probs=tinyP splat + mask outputs (reads only 2MB g_pk) */
__global__ __launch_bounds__(256) void k_fill(float* __restrict__ out, int mode){
  int row = blockIdx.y;
  float tinyP = g_params[row*8+3];
  float4 f = make_float4(tinyP, tinyP, tinyP, tinyP);
  int base = blockIdx.x*CHUNK4;
  float4* o4 = ((float4*)(out + (size_t)row*NV)) + base;
  if (mode == 0){
    for (int i = threadIdx.x; i < CHUNK4; i += 256) o4[i] = f;
  } else if (mode == 1){
    const unsigned* pkrow = g_pk + (size_t)row*NW;
    float4* pm4 = ((float4*)(out + (size_t)NB*NV + (size_t)row*NV)) + base;
    float4* om4 = ((float4*)(out + 2*(size_t)NB*NV + (size_t)row*NV)) + base;
    for (int i = threadIdx.x; i < CHUNK4; i += 256){
      unsigned m8 = mask8(pkrow, base + i);
      float4 pm, om;
      pm.x = (m8 & 0x01u) ? 1.f : 0.f;  om.x = (m8 & 0x02u) ? 1.f : 0.f;
      pm.y = (m8 & 0x04u) ? 1.f : 0.f;  om.y = (m8 & 0x08u) ? 1.f : 0.f;
      pm.z = (m8 & 0x10u) ? 1.f : 0.f;  om.z = (m8 & 0x20u) ? 1.f : 0.f;
      pm.w = (m8 & 0x40u) ? 1.f : 0.f;  om.w = (m8 & 0x80u) ? 1.f : 0.f;
      o4[i] = f; pm4[i] = pm; om4[i] = om;
    }
  } else {
    const unsigned* pkrow = g_pk + (size_t)row*NW;
    unsigned char* bp = (unsigned char*)out + (size_t)NB*NV*4;
    uchar4* pm4 = ((uchar4*)(bp + (size_t)row*NV)) + base;
    uchar4* om4 = ((uchar4*)(bp + (size_t)NB*NV + (size_t)row*NV)) + base;
    for (int i = threadIdx.x; i < CHUNK4; i += 256){
      unsigned m8 = mask8(pkrow, base + i);
      uchar4 pm, om;
      pm.x = (m8 & 0x01u) ? 1 : 0;  om.x = (m8 & 0x02u) ? 1 : 0;
      pm.y = (m8 & 0x04u) ? 1 : 0;  om.y = (m8 & 0x08u) ? 1 : 0;
      pm.z = (m8 & 0x10u) ? 1 : 0;  om.z = (m8 & 0x20u) ? 1 : 0;
      pm.w = (m8 & 0x40u) ? 1 : 0;  om.w = (m8 & 0x80u) ? 1 : 0;
      o4[i] = f; pm4[i] = pm; om4[i] = om;
    }
  }
}

/* sparse survivor writes (runs after fill) */
__global__ __launch_bounds__(256) void k_spray(float* __restrict__ out){
  int row = blockIdx.x;
  float thrf = g_params[row*8+0], M = g_params[row*8+1], invZ2 = g_params[row*8+2];
  int idx_cut = __float_as_int(g_params[row*8+4]);
  int count = g_candcnt[row]; if (count > CAP) count = CAP;
  const float* cand = g_cand + row*CAP;
  const int* cidx = g_cidx + row*CAP;
  for (int i = threadIdx.x; i < count; i += 256){
    float v = cand[i];
    int gi = cidx[i];
    if ((v > thrf) || (v == thrf && gi >= idx_cut))
      out[(size_t)row*NV + gi] = expf(v - M) * invZ2;
  }
}

extern "C" void kernel_launch(void* const* d_in, const int* in_sizes, int n_in,
                              void* d_out, int out_size) {
  /* size-based input resolution (robust to dict vs alphabetical metadata order) */
  int il = -1, t0 = -1, t1 = -1;
  for (int i = 0; i < n_in; i++){
    if (in_sizes[i] == NB*NV && il < 0) il = i;
    else if (in_sizes[i] > NB){ if (t0 < 0) t0 = i; else t1 = i; }
  }
  int ip, io;
  if (in_sizes[t0] >= in_sizes[t1]){ ip = t0; io = t1; } else { ip = t1; io = t0; }
  int s[6], ns = 0;
  for (int i = 0; i < n_in; i++)
    if (i != il && i != ip && i != io && ns < 6) s[ns++] = i;
  int ipres = (ip < io) ? s[0] : s[1];
  int irep = s[2], itemp = s[3], itopk = s[4], itopp = s[5];

  const float* logits = (const float*)d_in[il];
  const int*   ptoks  = (const int*)d_in[ip];
  const int*   otoks  = (const int*)d_in[io];
  const float* pres   = (const float*)d_in[ipres];
  const float* rep    = (const float*)d_in[irep];
  const float* temp   = (const float*)d_in[itemp];
  const int*   tk     = (const int*)d_in[itopk];
  const float* tp     = (const float*)d_in[itopp];
  float* out = (float*)d_out;

  int PL = in_sizes[ip] / NB;
  int OL = in_sizes[io] / NB;

  long long bv = (long long)NB * NV;
  int mode = 0;
  if ((long long)out_size >= 3*bv) mode = 1;                 /* masks as float */
  else if ((long long)out_size >= bv + bv/2) mode = 2;       /* masks as bytes */

  k_init<<<512, 256>>>();
  k_scatter<<<(NB*PL + 255)/256, 256>>>(ptoks, PL, 1u);
  k_scatter<<<(NB*OL + 255)/256, 256>>>(otoks, OL, 2u);
  dim3 grid(BPR, NB);
  k_pass1<<<grid, 256>>>(logits, pres, rep, temp);
  k_select<<<NB, 256>>>(logits, pres, rep, temp, tk, tp);
  k_fill<<<grid, 256>>>(out, mode);
  k_spray<<<NB, 256>>>(out);
}

// round 11
// speedup vs baseline: 1.1453x; 1.0226x over previous
#include <cuda_runtime.h>
#include <math.h>
#include <limits.h>

#define NB 128
#define NV 128000
#define N4 (NV/4)
#define NW (NV/16)        /* packed mask words per row (16 tokens/word) */
#define BPR 32
#define CHUNK4 (N4/BPR)   /* 1000 float4 per block */
#define TINYV 6.103515625e-05f
#define SEPS 1e-05f
#define CAP 8192
#define SCAP 256
#define SBUF 2048

__device__ unsigned g_pk[(size_t)NB*NW];   /* 2 bits/token: bit0 prompt, bit1 output */
__device__ int g_candcnt[NB];
__device__ float g_cand[NB*CAP];           /* EXACT candidate x values */
__device__ int g_cidx[NB*CAP];
__device__ float g_params[NB*8];

__device__ __forceinline__ unsigned ofl(float f){
  unsigned u = __float_as_uint(f);
  return (u & 0x80000000u) ? ~u : (u | 0x80000000u);
}
__device__ __forceinline__ float ifl(unsigned u){
  return __uint_as_float((u & 0x80000000u) ? (u & 0x7FFFFFFFu) : ~u);
}
/* EXACT mirror of reference arithmetic: l/pen (or l*pen), -pp, /temp */
__device__ __forceinline__ float xform(float l, unsigned mb, float rp, float pp, float tv){
  float x = l;
  if (mb){
    x = (l > 0.f) ? __fdiv_rn(l, rp) : __fmul_rn(l, rp);
    if (mb & 2u) x = __fsub_rn(x, pp);
  }
  return __fdiv_rn(x, tv);
}
/* FAST penalized logit in y-space (no temperature; ordering is tv-invariant) */
__device__ __forceinline__ float yfast(float l, unsigned mb, float rp, float rrp, float pp){
  float y = (l > 0.f) ? l*rrp : l*rp;
  if (mb & 2u) y -= pp;
  return y;
}
__device__ __forceinline__ unsigned mask8(const unsigned* __restrict__ pk, int i){
  unsigned w = pk[i >> 2];
  return (w >> ((i & 3) << 3)) & 0xFFu;
}

__global__ void k_init(){
  size_t i0 = (size_t)blockIdx.x*blockDim.x + threadIdx.x;
  size_t n = (size_t)NB*NW;
  for (size_t i = i0; i < n; i += (size_t)gridDim.x*blockDim.x) g_pk[i] = 0u;
  if (i0 < NB) g_candcnt[i0] = 0;
}

__global__ void k_scatter(const int* __restrict__ toks, int L, unsigned bit){
  int i = blockIdx.x*blockDim.x + threadIdx.x;
  if (i >= NB*L) return;
  int row = i / L;
  int t = toks[i];
  if (t >= 0 && t < NV)
    atomicOr(&g_pk[(size_t)row*NW + (t >> 4)], bit << ((t & 15)*2));
}

/* fused: chunk y-max + mask emission + superset candidate collection
   (R8 coalesced layout; y-space fast path for unmasked groups) */
__global__ __launch_bounds__(256) void k_pass1(
  const float* __restrict__ logits, const float* __restrict__ presence,
  const float* __restrict__ rep, const float* __restrict__ temp,
  float* __restrict__ out, int mode)
{
  __shared__ float s_red[8];
  __shared__ float s_bmax;
  __shared__ float sb_v[SBUF];
  __shared__ int   sb_i[SBUF];
  __shared__ unsigned sb_n;
  __shared__ unsigned sb_base;

  int row = blockIdx.y;
  float rp = rep[row], pp = presence[row];
  float tv = temp[row]; if (tv < SEPS) tv = 1.f;
  float rrp = __fdividef(1.f, rp);
  int base = blockIdx.x*CHUNK4;
  const float4* l4 = ((const float4*)(logits + (size_t)row*NV)) + base;
  const unsigned* pkrow = g_pk + (size_t)row*NW;

  if (threadIdx.x == 0) sb_n = 0;

  /* loop 1: y-space chunk max */
  float ym = -INFINITY;
  for (int i = threadIdx.x; i < CHUNK4; i += 256){
    float4 l = l4[i];
    unsigned m8 = mask8(pkrow, base + i);
    float a, b, c, d;
    if (m8 == 0u){ a = l.x; b = l.y; c = l.z; d = l.w; }
    else {
      a = (m8 & 0x03u) ? yfast(l.x, m8     , rp, rrp, pp) : l.x;
      b = (m8 & 0x0Cu) ? yfast(l.y, m8 >> 2, rp, rrp, pp) : l.y;
      c = (m8 & 0x30u) ? yfast(l.z, m8 >> 4, rp, rrp, pp) : l.z;
      d = (m8 & 0xC0u) ? yfast(l.w, m8 >> 6, rp, rrp, pp) : l.w;
    }
    ym = fmaxf(fmaxf(ym, fmaxf(a, b)), fmaxf(c, d));
  }
  #pragma unroll
  for (int o = 16; o > 0; o >>= 1) ym = fmaxf(ym, __shfl_xor_sync(0xFFFFFFFFu, ym, o));
  if ((threadIdx.x & 31) == 0) s_red[threadIdx.x >> 5] = ym;
  __syncthreads();
  if (threadIdx.x == 0){
    float v = s_red[0];
    #pragma unroll
    for (int w = 1; w < 8; w++) v = fmaxf(v, s_red[w]);
    s_bmax = v;
  }
  __syncthreads();
  /* y-space superset cut: tv<=1 -> 0.52 > 0.5*tv, plus approx-error margin */
  float cut = s_bmax - 0.38f*fabsf(s_bmax) - 0.54f;

  /* mask emission (pk is L1-resident; coalesced stores) */
  if (mode == 1){
    float4* pm4 = ((float4*)(out + (size_t)NB*NV + (size_t)row*NV)) + base;
    float4* om4 = ((float4*)(out + 2*(size_t)NB*NV + (size_t)row*NV)) + base;
    for (int i = threadIdx.x; i < CHUNK4; i += 256){
      unsigned m8 = mask8(pkrow, base + i);
      float4 pm, om;
      pm.x = (m8 & 0x01u) ? 1.f : 0.f;  om.x = (m8 & 0x02u) ? 1.f : 0.f;
      pm.y = (m8 & 0x04u) ? 1.f : 0.f;  om.y = (m8 & 0x08u) ? 1.f : 0.f;
      pm.z = (m8 & 0x10u) ? 1.f : 0.f;  om.z = (m8 & 0x20u) ? 1.f : 0.f;
      pm.w = (m8 & 0x40u) ? 1.f : 0.f;  om.w = (m8 & 0x80u) ? 1.f : 0.f;
      pm4[i] = pm; om4[i] = om;
    }
  } else if (mode == 2){
    unsigned char* bp = (unsigned char*)out + (size_t)NB*NV*4;
    uchar4* pm4 = ((uchar4*)(bp + (size_t)row*NV)) + base;
    uchar4* om4 = ((uchar4*)(bp + (size_t)NB*NV + (size_t)row*NV)) + base;
    for (int i = threadIdx.x; i < CHUNK4; i += 256){
      unsigned m8 = mask8(pkrow, base + i);
      uchar4 pm, om;
      pm.x = (m8 & 0x01u) ? 1 : 0;  om.x = (m8 & 0x02u) ? 1 : 0;
      pm.y = (m8 & 0x04u) ? 1 : 0;  om.y = (m8 & 0x08u) ? 1 : 0;
      pm.z = (m8 & 0x10u) ? 1 : 0;  om.z = (m8 & 0x20u) ? 1 : 0;
      pm.w = (m8 & 0x40u) ? 1 : 0;  om.w = (m8 & 0x80u) ? 1 : 0;
      pm4[i] = pm; om4[i] = om;
    }
  }

  /* loop 2: candidate collection (y-space compare, exact x store) */
  for (int i = threadIdx.x; i < CHUNK4; i += 256){
    float4 l = l4[i];                                   /* L1 hit */
    unsigned m8 = mask8(pkrow, base + i);
    float lv[4] = {l.x, l.y, l.z, l.w};
    if (m8 == 0u){
      #pragma unroll
      for (int j = 0; j < 4; j++){
        if (lv[j] >= cut){
          float ex = __fdiv_rn(lv[j], tv);              /* exact, rare */
          unsigned id = atomicAdd(&sb_n, 1u);
          if (id < SBUF){ sb_v[id] = ex; sb_i[id] = (base + i)*4 + j; }
          else {
            int p = atomicAdd(&g_candcnt[row], 1);
            if (p < CAP){ g_cand[row*CAP + p] = ex; g_cidx[row*CAP + p] = (base + i)*4 + j; }
          }
        }
      }
    } else {
      #pragma unroll
      for (int j = 0; j < 4; j++){
        unsigned mb = (m8 >> (2*j)) & 3u;
        float y = mb ? yfast(lv[j], mb, rp, rrp, pp) : lv[j];
        if (y >= cut){
          float ex = xform(lv[j], mb, rp, pp, tv);      /* exact, rare */
          unsigned id = atomicAdd(&sb_n, 1u);
          if (id < SBUF){ sb_v[id] = ex; sb_i[id] = (base + i)*4 + j; }
          else {
            int p = atomicAdd(&g_candcnt[row], 1);
            if (p < CAP){ g_cand[row*CAP + p] = ex; g_cidx[row*CAP + p] = (base + i)*4 + j; }
          }
        }
      }
    }
  }
  __syncthreads();
  unsigned n = sb_n; if (n > SBUF) n = SBUF;
  if (threadIdx.x == 0) sb_base = (unsigned)atomicAdd(&g_candcnt[row], (int)n);
  __syncthreads();
  unsigned b0 = sb_base;
  for (unsigned i = threadIdx.x; i < n; i += 256){
    unsigned p = b0 + i;
    if (p < CAP){ g_cand[row*CAP + p] = sb_v[i]; g_cidx[row*CAP + p] = sb_i[i]; }
  }
}

__global__ __launch_bounds__(256) void k_select(
  const float* __restrict__ logits, const float* __restrict__ presence,
  const float* __restrict__ rep, const float* __restrict__ temp,
  const int* __restrict__ topk, const float* __restrict__ topp)
{
  __shared__ unsigned s_hist[256];
  __shared__ float s_small[SCAP];
  __shared__ float s_e[SCAP];
  __shared__ double s_d[SCAP];
  __shared__ unsigned s_cnt;
  __shared__ unsigned s_maxu;
  __shared__ int s_sel, s_want, s_jstar;

  int row = blockIdx.x, tid = threadIdx.x;
  int kneed = topk[row]; if (kneed < 1) kneed = 1; if (kneed > NV) kneed = NV;
  float tp = topp[row];
  int count = g_candcnt[row];
  float* cand = g_cand + row*CAP;
  int* cidx = g_cidx + row*CAP;

  /* exact row max from exact candidates */
  if (tid == 0) s_maxu = 0u;
  __syncthreads();
  {
    int c0 = count > CAP ? CAP : count;
    float lm = -INFINITY;
    for (int i = tid; i < c0; i += 256) lm = fmaxf(lm, cand[i]);
    #pragma unroll
    for (int o = 16; o > 0; o >>= 1) lm = fmaxf(lm, __shfl_xor_sync(0xFFFFFFFFu, lm, o));
    if ((tid & 31) == 0) atomicMax(&s_maxu, ofl(lm));
  }
  __syncthreads();
  float M = ifl(s_maxu);

  if (!(count >= kneed && count <= CAP)){
    /* fallback: bracketed exact search (cold path) */
    float rp = rep[row], pp = presence[row];
    float tv = temp[row]; if (tv < SEPS) tv = 1.f;
    const float4* l4 = (const float4*)(logits + (size_t)row*NV);
    const unsigned* pkrow = g_pk + (size_t)row*NW;
    float delta = 0.38f*fabsf(M) + 0.5f;
    float dlo = 0.f, dhi = -1.f;
    if (count < kneed){ dlo = delta; delta *= 2.f; }
    else              { dhi = delta; delta *= 0.5f; }
    for (int it = 0; it < 64; it++){
      float c2 = M - delta;
      if (tid == 0) s_cnt = 0;
      __syncthreads();
      for (int i = tid; i < N4; i += 256){
        float4 l = l4[i];
        unsigned m8 = mask8(pkrow, i);
        float v[4];
        v[0] = xform(l.x, (m8     )&3u, rp, pp, tv);
        v[1] = xform(l.y, (m8 >> 2)&3u, rp, pp, tv);
        v[2] = xform(l.z, (m8 >> 4)&3u, rp, pp, tv);
        v[3] = xform(l.w, (m8 >> 6)&3u, rp, pp, tv);
        #pragma unroll
        for (int j = 0; j < 4; j++){
          if (v[j] >= c2){
            unsigned id = atomicAdd(&s_cnt, 1u);
            if (id < CAP){ cand[id] = v[j]; cidx[id] = i*4 + j; }
          }
        }
      }
      __syncthreads();
      count = (int)s_cnt;
      __syncthreads();
      if (count >= kneed && count <= CAP) break;
      if (count < kneed){ dlo = delta; delta = (dhi > 0.f) ? 0.5f*(delta + dhi) : delta*2.f; }
      else              { dhi = delta; delta = 0.5f*(dlo + delta); }
    }
    if (count > CAP) count = CAP;
    if (count < kneed) kneed = count;
    if (tid == 0) s_maxu = 0u;
    __syncthreads();
    float lm = -INFINITY;
    for (int i = tid; i < count; i += 256) lm = fmaxf(lm, cand[i]);
    #pragma unroll
    for (int o = 16; o > 0; o >>= 1) lm = fmaxf(lm, __shfl_xor_sync(0xFFFFFFFFu, lm, o));
    if ((tid & 31) == 0) atomicMax(&s_maxu, ofl(lm));
    __syncthreads();
    M = ifl(s_maxu);
  }
  __syncthreads();
  if (tid == 0) g_candcnt[row] = count;   /* publish final count for k_spray */

  /* radix-select k-th largest value */
  unsigned prefix = 0; int want = kneed;
  for (int shift = 24; shift >= 0; shift -= 8){
    s_hist[tid] = 0;
    __syncthreads();
    unsigned himask = (shift == 24) ? 0u : (0xFFFFFFFFu << (shift + 8));
    for (int i = tid; i < count; i += 256){
      unsigned ou = ofl(cand[i]);
      if ((ou & himask) == prefix) atomicAdd(&s_hist[(ou >> shift) & 255u], 1u);
    }
    __syncthreads();
    if (tid == 0){
      int c = 0, b = 255;
      for (; b > 0; b--){
        int h = (int)s_hist[b];
        if (c + h >= want) break;
        c += h;
      }
      s_sel = b; s_want = want - c;
    }
    __syncthreads();
    prefix |= ((unsigned)s_sel) << shift;
    want = s_want;
    __syncthreads();
  }
  float thr = ifl(prefix);

  /* gather survivors >= thr */
  if (tid == 0) s_cnt = 0;
  __syncthreads();
  for (int i = tid; i < count; i += 256){
    float v = cand[i];
    if (v >= thr){
      unsigned id = atomicAdd(&s_cnt, 1u);
      if (id < SCAP) s_small[id] = v;
    }
  }
  __syncthreads();
  int m = (int)s_cnt; if (m > SCAP) m = SCAP;
  if (tid >= m) s_small[tid] = -INFINITY;
  __syncthreads();

  /* bitonic sort descending */
  for (int k = 2; k <= SCAP; k <<= 1){
    for (int j = k >> 1; j > 0; j >>= 1){
      int ixj = tid ^ j;
      if (ixj > tid){
        float a = s_small[tid], b = s_small[ixj];
        bool desc = ((tid & k) == 0);
        if (desc ? (a < b) : (a > b)){ s_small[tid] = b; s_small[ixj] = a; }
      }
      __syncthreads();
    }
  }
  float ex_tiny = expf(__fsub_rn(TINYV, M));
  s_e[tid] = (tid < m) ? expf(s_small[tid] - M) : 0.f;
  __syncthreads();

  /* parallel suffix sums */
  s_d[tid] = (double)s_e[tid];
  __syncthreads();
  #pragma unroll
  for (int off = 1; off < SCAP; off <<= 1){
    double add = (tid + off < SCAP) ? s_d[tid + off] : 0.0;
    __syncthreads();
    s_d[tid] += add;
    __syncthreads();
  }
  double T = (double)(NV - m) * (double)ex_tiny;
  double Z1 = T + s_d[0];
  double need = (double)__fsub_rn(1.0f, tp) * Z1;
  if (tid == 0) s_jstar = 0;
  __syncthreads();
  if (tid < m && (T + s_d[tid]) > need) atomicMax(&s_jstar, tid);
  __syncthreads();

  if (tid == 0){
    int jstar = s_jstar;
    float thrf = s_small[jstar];
    int nsel = jstar + 1;

    /* tie handling at top-p boundary (stable argsort keeps larger token idx) */
    int lo = jstar;
    while (lo > 0 && s_small[lo-1] == thrf) lo--;
    int q = jstar - lo + 1;
    int dcnt = 0;
    for (int i = jstar; i < m && s_small[i] == thrf; i++) dcnt++;
    dcnt += q - 1;
    int idx_cut = INT_MIN;
    if (q < dcnt){
      int idxs[64]; int dt = 0;
      for (int i = 0; i < count && dt < 64; i++)
        if (cand[i] == thrf) idxs[dt++] = cidx[i];
      if (q < dt){
        for (int a = 0; a < q; a++){
          int best = a;
          for (int b2 = a+1; b2 < dt; b2++) if (idxs[b2] > idxs[best]) best = b2;
          int t2 = idxs[a]; idxs[a] = idxs[best]; idxs[best] = t2;
        }
        idx_cut = idxs[q-1];
      }
    }

    double Zsel = s_d[0] - ((jstar+1 < SCAP) ? s_d[jstar+1] : 0.0);
    double Z2 = (double)(NV - nsel) * (double)ex_tiny + Zsel;
    float Z2f = (float)Z2;
    float invZ2 = 1.0f / Z2f;
    g_params[row*8+0] = thrf;
    g_params[row*8+1] = M;
    g_params[row*8+2] = invZ2;
    g_params[row*8+3] = __fdiv_rn(ex_tiny, Z2f);
    g_params[row*8+4] = __int_as_float(idx_cut);
  }
}

/* pure-write splat of per-row tiny prob */
__global__ __launch_bounds__(256) void k_fill(float* __restrict__ out){
  int row = blockIdx.y;
  float tinyP = g_params[row*8+3];
  float4 f = make_float4(tinyP, tinyP, tinyP, tinyP);
  float4* o4 = ((float4*)(out + (size_t)row*NV)) + blockIdx.x*CHUNK4;
  for (int i = threadIdx.x; i < CHUNK4; i += 256) o4[i] = f;
}

/* sparse survivor writes (runs after fill) */
__global__ __launch_bounds__(256) void k_spray(float* __restrict__ out){
  int row = blockIdx.x;
  float thrf = g_params[row*8+0], M = g_params[row*8+1], invZ2 = g_params[row*8+2];
  int idx_cut = __float_as_int(g_params[row*8+4]);
  int count = g_candcnt[row]; if (count > CAP) count = CAP;
  const float* cand = g_cand + row*CAP;
  const int* cidx = g_cidx + row*CAP;
  for (int i = threadIdx.x; i < count; i += 256){
    float v = cand[i];
    int gi = cidx[i];
    if ((v > thrf) || (v == thrf && gi >= idx_cut))
      out[(size_t)row*NV + gi] = expf(v - M) * invZ2;
  }
}

extern "C" void kernel_launch(void* const* d_in, const int* in_sizes, int n_in,
                              void* d_out, int out_size) {
  /* size-based input resolution (robust to dict vs alphabetical metadata order) */
  int il = -1, t0 = -1, t1 = -1;
  for (int i = 0; i < n_in; i++){
    if (in_sizes[i] == NB*NV && il < 0) il = i;
    else if (in_sizes[i] > NB){ if (t0 < 0) t0 = i; else t1 = i; }
  }
  int ip, io;
  if (in_sizes[t0] >= in_sizes[t1]){ ip = t0; io = t1; } else { ip = t1; io = t0; }
  int s[6], ns = 0;
  for (int i = 0; i < n_in; i++)
    if (i != il && i != ip && i != io && ns < 6) s[ns++] = i;
  int ipres = (ip < io) ? s[0] : s[1];
  int irep = s[2], itemp = s[3], itopk = s[4], itopp = s[5];

  const float* logits = (const float*)d_in[il];
  const int*   ptoks  = (const int*)d_in[ip];
  const int*   otoks  = (const int*)d_in[io];
  const float* pres   = (const float*)d_in[ipres];
  const float* rep    = (const float*)d_in[irep];
  const float* temp   = (const float*)d_in[itemp];
  const int*   tk     = (const int*)d_in[itopk];
  const float* tp     = (const float*)d_in[itopp];
  float* out = (float*)d_out;

  int PL = in_sizes[ip] / NB;
  int OL = in_sizes[io] / NB;

  long long bv = (long long)NB * NV;
  int mode = 0;
  if ((long long)out_size >= 3*bv) mode = 1;                 /* masks as float */
  else if ((long long)out_size >= bv + bv/2) mode = 2;       /* masks as bytes */

  k_init<<<512, 256>>>();
  k_scatter<<<(NB*PL + 255)/256, 256>>>(ptoks, PL, 1u);
  k_scatter<<<(NB*OL + 255)/256, 256>>>(otoks, OL, 2u);
  dim3 grid(BPR, NB);
  k_pass1<<<grid, 256>>>(logits, pres, rep, temp, out, mode);
  k_select<<<NB, 256>>>(logits, pres, rep, temp, tk, tp);
  k_fill<<<grid, 256>>>(out);
  k_spray<<<NB, 256>>>(out);
}

// round 12
// speedup vs baseline: 1.2034x; 1.0508x over previous
#include <cuda_runtime.h>
#include <math.h>
#include <limits.h>

#define NB 128
#define NV 128000
#define N4 (NV/4)
#define NW (NV/16)        /* packed mask words per row (16 tokens/word) */
#define BPR 32
#define CHUNK4 (N4/BPR)   /* 1000 float4 per block */
#define TINYV 6.103515625e-05f
#define SEPS 1e-05f
#define CAP 8192
#define SCAP 256
#define SBUF 2048

__device__ unsigned g_pk[(size_t)NB*NW];   /* 2 bits/token: bit0 prompt, bit1 output */
__device__ int g_candcnt[NB];              /* starts 0; reset by k_spray each run */
__device__ float g_cand[NB*CAP];           /* EXACT candidate x values */
__device__ int g_cidx[NB*CAP];
__device__ float g_params[NB*8];

__device__ __forceinline__ unsigned ofl(float f){
  unsigned u = __float_as_uint(f);
  return (u & 0x80000000u) ? ~u : (u | 0x80000000u);
}
__device__ __forceinline__ float ifl(unsigned u){
  return __uint_as_float((u & 0x80000000u) ? (u & 0x7FFFFFFFu) : ~u);
}
/* EXACT mirror of reference arithmetic: l/pen (or l*pen), -pp, /temp */
__device__ __forceinline__ float xform(float l, unsigned mb, float rp, float pp, float tv){
  float x = l;
  if (mb){
    x = (l > 0.f) ? __fdiv_rn(l, rp) : __fmul_rn(l, rp);
    if (mb & 2u) x = __fsub_rn(x, pp);
  }
  return __fdiv_rn(x, tv);
}
/* FAST penalized logit in y-space (no temperature; ordering is tv-invariant) */
__device__ __forceinline__ float yfast(float l, unsigned mb, float rp, float rrp, float pp){
  float y = (l > 0.f) ? l*rrp : l*rp;
  if (mb & 2u) y -= pp;
  return y;
}
__device__ __forceinline__ unsigned mask8(const unsigned* __restrict__ pk, int i){
  unsigned w = pk[i >> 2];
  return (w >> ((i & 3) << 3)) & 0xFFu;
}

/* both token scatters in one launch */
__global__ void k_scatter2(const int* __restrict__ ptoks, int PL,
                           const int* __restrict__ otoks, int OL, int npb){
  if ((int)blockIdx.x < npb){
    int i = blockIdx.x*256 + threadIdx.x;
    if (i < NB*PL){
      int row = i / PL, t = ptoks[i];
      if (t >= 0 && t < NV)
        atomicOr(&g_pk[(size_t)row*NW + (t >> 4)], 1u << ((t & 15)*2));
    }
  } else {
    int i = (blockIdx.x - npb)*256 + threadIdx.x;
    if (i < NB*OL){
      int row = i / OL, t = otoks[i];
      if (t >= 0 && t < NV)
        atomicOr(&g_pk[(size_t)row*NW + (t >> 4)], 2u << ((t & 15)*2));
    }
  }
}

/* fused: chunk y-max + mask emission + superset candidate collection (R11-proven) */
__global__ __launch_bounds__(256) void k_pass1(
  const float* __restrict__ logits, const float* __restrict__ presence,
  const float* __restrict__ rep, const float* __restrict__ temp,
  float* __restrict__ out, int mode)
{
  __shared__ float s_red[8];
  __shared__ float s_bmax;
  __shared__ float sb_v[SBUF];
  __shared__ int   sb_i[SBUF];
  __shared__ unsigned sb_n;
  __shared__ unsigned sb_base;

  int row = blockIdx.y;
  float rp = rep[row], pp = presence[row];
  float tv = temp[row]; if (tv < SEPS) tv = 1.f;
  float rrp = __fdividef(1.f, rp);
  int base = blockIdx.x*CHUNK4;
  const float4* l4 = ((const float4*)(logits + (size_t)row*NV)) + base;
  const unsigned* pkrow = g_pk + (size_t)row*NW;

  if (threadIdx.x == 0) sb_n = 0;

  float ym = -INFINITY;
  for (int i = threadIdx.x; i < CHUNK4; i += 256){
    float4 l = l4[i];
    unsigned m8 = mask8(pkrow, base + i);
    float a, b, c, d;
    if (m8 == 0u){ a = l.x; b = l.y; c = l.z; d = l.w; }
    else {
      a = (m8 & 0x03u) ? yfast(l.x, m8     , rp, rrp, pp) : l.x;
      b = (m8 & 0x0Cu) ? yfast(l.y, m8 >> 2, rp, rrp, pp) : l.y;
      c = (m8 & 0x30u) ? yfast(l.z, m8 >> 4, rp, rrp, pp) : l.z;
      d = (m8 & 0xC0u) ? yfast(l.w, m8 >> 6, rp, rrp, pp) : l.w;
    }
    ym = fmaxf(fmaxf(ym, fmaxf(a, b)), fmaxf(c, d));
  }
  #pragma unroll
  for (int o = 16; o > 0; o >>= 1) ym = fmaxf(ym, __shfl_xor_sync(0xFFFFFFFFu, ym, o));
  if ((threadIdx.x & 31) == 0) s_red[threadIdx.x >> 5] = ym;
  __syncthreads();
  if (threadIdx.x == 0){
    float v = s_red[0];
    #pragma unroll
    for (int w = 1; w < 8; w++) v = fmaxf(v, s_red[w]);
    s_bmax = v;
  }
  __syncthreads();
  float cut = s_bmax - 0.38f*fabsf(s_bmax) - 0.54f;  /* y-space superset cut */

  if (mode == 1){
    float4* pm4 = ((float4*)(out + (size_t)NB*NV + (size_t)row*NV)) + base;
    float4* om4 = ((float4*)(out + 2*(size_t)NB*NV + (size_t)row*NV)) + base;
    for (int i = threadIdx.x; i < CHUNK4; i += 256){
      unsigned m8 = mask8(pkrow, base + i);
      float4 pm, om;
      pm.x = (m8 & 0x01u) ? 1.f : 0.f;  om.x = (m8 & 0x02u) ? 1.f : 0.f;
      pm.y = (m8 & 0x04u) ? 1.f : 0.f;  om.y = (m8 & 0x08u) ? 1.f : 0.f;
      pm.z = (m8 & 0x10u) ? 1.f : 0.f;  om.z = (m8 & 0x20u) ? 1.f : 0.f;
      pm.w = (m8 & 0x40u) ? 1.f : 0.f;  om.w = (m8 & 0x80u) ? 1.f : 0.f;
      pm4[i] = pm; om4[i] = om;
    }
  } else if (mode == 2){
    unsigned char* bp = (unsigned char*)out + (size_t)NB*NV*4;
    uchar4* pm4 = ((uchar4*)(bp + (size_t)row*NV)) + base;
    uchar4* om4 = ((uchar4*)(bp + (size_t)NB*NV + (size_t)row*NV)) + base;
    for (int i = threadIdx.x; i < CHUNK4; i += 256){
      unsigned m8 = mask8(pkrow, base + i);
      uchar4 pm, om;
      pm.x = (m8 & 0x01u) ? 1 : 0;  om.x = (m8 & 0x02u) ? 1 : 0;
      pm.y = (m8 & 0x04u) ? 1 : 0;  om.y = (m8 & 0x08u) ? 1 : 0;
      pm.z = (m8 & 0x10u) ? 1 : 0;  om.z = (m8 & 0x20u) ? 1 : 0;
      pm.w = (m8 & 0x40u) ? 1 : 0;  om.w = (m8 & 0x80u) ? 1 : 0;
      pm4[i] = pm; om4[i] = om;
    }
  }

  for (int i = threadIdx.x; i < CHUNK4; i += 256){
    float4 l = l4[i];                                   /* L1 hit */
    unsigned m8 = mask8(pkrow, base + i);
    float lv[4] = {l.x, l.y, l.z, l.w};
    #pragma unroll
    for (int j = 0; j < 4; j++){
      unsigned mb = (m8 >> (2*j)) & 3u;
      float y = mb ? yfast(lv[j], mb, rp, rrp, pp) : lv[j];
      if (y >= cut){
        float ex = xform(lv[j], mb, rp, pp, tv);        /* exact, rare */
        unsigned id = atomicAdd(&sb_n, 1u);
        if (id < SBUF){ sb_v[id] = ex; sb_i[id] = (base + i)*4 + j; }
        else {
          int p = atomicAdd(&g_candcnt[row], 1);
          if (p < CAP){ g_cand[row*CAP + p] = ex; g_cidx[row*CAP + p] = (base + i)*4 + j; }
        }
      }
    }
  }
  __syncthreads();
  unsigned n = sb_n; if (n > SBUF) n = SBUF;
  if (threadIdx.x == 0) sb_base = (unsigned)atomicAdd(&g_candcnt[row], (int)n);
  __syncthreads();
  unsigned b0 = sb_base;
  for (unsigned i = threadIdx.x; i < n; i += 256){
    unsigned p = b0 + i;
    if (p < CAP){ g_cand[row*CAP + p] = sb_v[i]; g_cidx[row*CAP + p] = sb_i[i]; }
  }
}

__global__ __launch_bounds__(512) void k_select(
  const float* __restrict__ logits, const float* __restrict__ presence,
  const float* __restrict__ rep, const float* __restrict__ temp,
  const int* __restrict__ topk, const float* __restrict__ topp)
{
  __shared__ float s_cv[CAP];        /* 32 KB shared-resident candidates */
  __shared__ unsigned s_hist[256];
  __shared__ int s_suf[257];
  __shared__ float s_small[SCAP];
  __shared__ float s_e[SCAP];
  __shared__ double s_d[SCAP];
  __shared__ unsigned s_cnt;
  __shared__ unsigned s_maxu;
  __shared__ int s_sel, s_want, s_jstar;

  int row = blockIdx.x, tid = threadIdx.x;
  int kneed = topk[row]; if (kneed < 1) kneed = 1; if (kneed > NV) kneed = NV;
  float tp = topp[row];
  int count = g_candcnt[row];
  float* cand = g_cand + row*CAP;
  int* cidx = g_cidx + row*CAP;

  if (!(count >= kneed && count <= CAP)){
    /* fallback: bracketed exact search (cold path) */
    float rp = rep[row], pp = presence[row];
    float tv = temp[row]; if (tv < SEPS) tv = 1.f;
    const float4* l4 = (const float4*)(logits + (size_t)row*NV);
    const unsigned* pkrow = g_pk + (size_t)row*NW;
    float M0 = -INFINITY;   /* crude bound for bracketing */
    for (int i = tid; i < count && i < CAP; i += 512) M0 = fmaxf(M0, cand[i]);
    #pragma unroll
    for (int o = 16; o > 0; o >>= 1) M0 = fmaxf(M0, __shfl_xor_sync(0xFFFFFFFFu, M0, o));
    if (tid == 0) s_maxu = 0u;
    __syncthreads();
    if ((tid & 31) == 0) atomicMax(&s_maxu, ofl(M0));
    __syncthreads();
    float M = ifl(s_maxu); if (!isfinite(M)) M = 0.f;
    float delta = 0.38f*fabsf(M) + 0.5f;
    float dlo = 0.f, dhi = -1.f;
    if (count < kneed){ dlo = delta; delta *= 2.f; }
    else              { dhi = delta; delta *= 0.5f; }
    for (int it = 0; it < 64; it++){
      float c2 = M - delta;
      if (tid == 0) s_cnt = 0;
      __syncthreads();
      for (int i = tid; i < N4; i += 512){
        float4 l = l4[i];
        unsigned m8 = mask8(pkrow, i);
        float v[4];
        v[0] = xform(l.x, (m8     )&3u, rp, pp, tv);
        v[1] = xform(l.y, (m8 >> 2)&3u, rp, pp, tv);
        v[2] = xform(l.z, (m8 >> 4)&3u, rp, pp, tv);
        v[3] = xform(l.w, (m8 >> 6)&3u, rp, pp, tv);
        #pragma unroll
        for (int j = 0; j < 4; j++){
          if (v[j] >= c2){
            unsigned id = atomicAdd(&s_cnt, 1u);
            if (id < CAP){ cand[id] = v[j]; cidx[id] = i*4 + j; }
          }
        }
      }
      __syncthreads();
      count = (int)s_cnt;
      __syncthreads();
      if (count >= kneed && count <= CAP) break;
      if (count < kneed){ dlo = delta; delta = (dhi > 0.f) ? 0.5f*(delta + dhi) : delta*2.f; }
      else              { dhi = delta; delta = 0.5f*(dlo + delta); }
    }
    if (count > CAP) count = CAP;
    if (count < kneed) kneed = count;
  }
  __syncthreads();
  if (tid == 0) g_candcnt[row] = count;   /* publish final count for k_spray */

  /* stage candidates in shared */
  for (int i = tid; i < count; i += 512) s_cv[i] = cand[i];
  if (tid == 0) s_maxu = 0u;
  __syncthreads();

  /* exact row max */
  {
    float lm = -INFINITY;
    for (int i = tid; i < count; i += 512) lm = fmaxf(lm, s_cv[i]);
    #pragma unroll
    for (int o = 16; o > 0; o >>= 1) lm = fmaxf(lm, __shfl_xor_sync(0xFFFFFFFFu, lm, o));
    if ((tid & 31) == 0) atomicMax(&s_maxu, ofl(lm));
  }
  __syncthreads();
  float M = ifl(s_maxu);

  /* radix-select k-th largest (shared-resident, parallel bucket pick) */
  unsigned prefix = 0; int want = kneed;
  for (int shift = 24; shift >= 0; shift -= 8){
    if (tid < 256) s_hist[tid] = 0;
    __syncthreads();
    unsigned himask = (shift == 24) ? 0u : (0xFFFFFFFFu << (shift + 8));
    for (int i = tid; i < count; i += 512){
      unsigned ou = ofl(s_cv[i]);
      if ((ou & himask) == prefix) atomicAdd(&s_hist[(ou >> shift) & 255u], 1u);
    }
    __syncthreads();
    if (tid < 256) s_suf[tid] = (int)s_hist[tid];
    if (tid == 0) s_suf[256] = 0;
    __syncthreads();
    /* suffix-sum scan: s_suf[b] = sum_{j>=b} hist[j] */
    #pragma unroll
    for (int off = 1; off < 256; off <<= 1){
      int add = (tid < 256 && tid + off < 256) ? s_suf[tid + off] : 0;
      __syncthreads();
      if (tid < 256) s_suf[tid] += add;
      __syncthreads();
    }
    if (tid < 256){
      int sb = s_suf[tid], sb1 = (tid == 255) ? 0 : s_suf[tid + 1];
      if (sb >= want && sb1 < want){ s_sel = tid; s_want = want - sb1; }
    }
    __syncthreads();
    prefix |= ((unsigned)s_sel) << shift;
    want = s_want;
    __syncthreads();
  }
  float thr = ifl(prefix);

  /* gather survivors >= thr */
  if (tid == 0) s_cnt = 0;
  __syncthreads();
  for (int i = tid; i < count; i += 512){
    float v = s_cv[i];
    if (v >= thr){
      unsigned id = atomicAdd(&s_cnt, 1u);
      if (id < SCAP) s_small[id] = v;
    }
  }
  __syncthreads();
  int m = (int)s_cnt; if (m > SCAP) m = SCAP;
  if (tid >= m && tid < SCAP) s_small[tid] = -INFINITY;
  __syncthreads();

  /* bitonic sort descending (first 256 threads) */
  for (int k = 2; k <= SCAP; k <<= 1){
    for (int j = k >> 1; j > 0; j >>= 1){
      if (tid < SCAP){
        int ixj = tid ^ j;
        if (ixj > tid){
          float a = s_small[tid], b = s_small[ixj];
          bool desc = ((tid & k) == 0);
          if (desc ? (a < b) : (a > b)){ s_small[tid] = b; s_small[ixj] = a; }
        }
      }
      __syncthreads();
    }
  }
  float ex_tiny = expf(__fsub_rn(TINYV, M));
  if (tid < SCAP) s_e[tid] = (tid < m) ? expf(s_small[tid] - M) : 0.f;
  __syncthreads();

  /* parallel suffix sums over exp values */
  if (tid < SCAP) s_d[tid] = (double)s_e[tid];
  __syncthreads();
  #pragma unroll
  for (int off = 1; off < SCAP; off <<= 1){
    double add = (tid < SCAP && tid + off < SCAP) ? s_d[tid + off] : 0.0;
    __syncthreads();
    if (tid < SCAP) s_d[tid] += add;
    __syncthreads();
  }
  double T = (double)(NV - m) * (double)ex_tiny;
  double Z1 = T + s_d[0];
  double need = (double)__fsub_rn(1.0f, tp) * Z1;
  if (tid == 0) s_jstar = 0;
  __syncthreads();
  if (tid < m && (T + s_d[tid]) > need) atomicMax(&s_jstar, tid);
  __syncthreads();

  if (tid == 0){
    int jstar = s_jstar;
    float thrf = s_small[jstar];
    int nsel = jstar + 1;

    /* tie handling at top-p boundary (stable argsort keeps larger token idx) */
    int lo = jstar;
    while (lo > 0 && s_small[lo-1] == thrf) lo--;
    int q = jstar - lo + 1;
    int dcnt = 0;
    for (int i = jstar; i < m && s_small[i] == thrf; i++) dcnt++;
    dcnt += q - 1;
    int idx_cut = INT_MIN;
    if (q < dcnt){
      int idxs[64]; int dt = 0;
      for (int i = 0; i < count && dt < 64; i++)
        if (s_cv[i] == thrf) idxs[dt++] = cidx[i];
      if (q < dt){
        for (int a = 0; a < q; a++){
          int best = a;
          for (int b2 = a+1; b2 < dt; b2++) if (idxs[b2] > idxs[best]) best = b2;
          int t2 = idxs[a]; idxs[a] = idxs[best]; idxs[best] = t2;
        }
        idx_cut = idxs[q-1];
      }
    }

    double Zsel = s_d[0] - ((jstar+1 < SCAP) ? s_d[jstar+1] : 0.0);
    double Z2 = (double)(NV - nsel) * (double)ex_tiny + Zsel;
    float Z2f = (float)Z2;
    float invZ2 = 1.0f / Z2f;
    g_params[row*8+0] = thrf;
    g_params[row*8+1] = M;
    g_params[row*8+2] = invZ2;
    g_params[row*8+3] = __fdiv_rn(ex_tiny, Z2f);
    g_params[row*8+4] = __int_as_float(idx_cut);
  }
}

/* pure-write splat of per-row tiny prob */
__global__ __launch_bounds__(256) void k_fill(float* __restrict__ out){
  int row = blockIdx.y;
  float tinyP = g_params[row*8+3];
  float4 f = make_float4(tinyP, tinyP, tinyP, tinyP);
  float4* o4 = ((float4*)(out + (size_t)row*NV)) + blockIdx.x*CHUNK4;
  for (int i = threadIdx.x; i < CHUNK4; i += 256) o4[i] = f;
}

/* sparse survivor writes + end-of-graph cleanup (self-cleaning state) */
__global__ __launch_bounds__(256) void k_spray(
  float* __restrict__ out,
  const int* __restrict__ ptoks, int PL,
  const int* __restrict__ otoks, int OL, int npb)
{
  if ((int)blockIdx.x < NB){
    int row = blockIdx.x;
    float thrf = g_params[row*8+0], M = g_params[row*8+1], invZ2 = g_params[row*8+2];
    int idx_cut = __float_as_int(g_params[row*8+4]);
    int count = g_candcnt[row]; if (count > CAP) count = CAP;
    const float* cand = g_cand + row*CAP;
    const int* cidx = g_cidx + row*CAP;
    for (int i = threadIdx.x; i < count; i += 256){
      float v = cand[i];
      int gi = cidx[i];
      if ((v > thrf) || (v == thrf && gi >= idx_cut))
        out[(size_t)row*NV + gi] = expf(v - M) * invZ2;
    }
    if (threadIdx.x == 0) g_candcnt[row] = 0;          /* reset for next replay */
  } else {
    int b = blockIdx.x - NB;                            /* clear g_pk via token lists */
    if (b < npb){
      int i = b*256 + threadIdx.x;
      if (i < NB*PL){
        int row = i / PL, t = ptoks[i];
        if (t >= 0 && t < NV) g_pk[(size_t)row*NW + (t >> 4)] = 0u;
      }
    } else {
      int i = (b - npb)*256 + threadIdx.x;
      if (i < NB*OL){
        int row = i / OL, t = otoks[i];
        if (t >= 0 && t < NV) g_pk[(size_t)row*NW + (t >> 4)] = 0u;
      }
    }
  }
}

extern "C" void kernel_launch(void* const* d_in, const int* in_sizes, int n_in,
                              void* d_out, int out_size) {
  /* size-based input resolution (robust to dict vs alphabetical metadata order) */
  int il = -1, t0 = -1, t1 = -1;
  for (int i = 0; i < n_in; i++){
    if (in_sizes[i] == NB*NV && il < 0) il = i;
    else if (in_sizes[i] > NB){ if (t0 < 0) t0 = i; else t1 = i; }
  }
  int ip, io;
  if (in_sizes[t0] >= in_sizes[t1]){ ip = t0; io = t1; } else { ip = t1; io = t0; }
  int s[6], ns = 0;
  for (int i = 0; i < n_in; i++)
    if (i != il && i != ip && i != io && ns < 6) s[ns++] = i;
  int ipres = (ip < io) ? s[0] : s[1];
  int irep = s[2], itemp = s[3], itopk = s[4], itopp = s[5];

  const float* logits = (const float*)d_in[il];
  const int*   ptoks  = (const int*)d_in[ip];
  const int*   otoks  = (const int*)d_in[io];
  const float* pres   = (const float*)d_in[ipres];
  const float* rep    = (const float*)d_in[irep];
  const float* temp   = (const float*)d_in[itemp];
  const int*   tk     = (const int*)d_in[itopk];
  const float* tp     = (const float*)d_in[itopp];
  float* out = (float*)d_out;

  int PL = in_sizes[ip] / NB;
  int OL = in_sizes[io] / NB;
  int npb = (NB*PL + 255)/256;
  int nob = (NB*OL + 255)/256;

  long long bv = (long long)NB * NV;
  int mode = 0;
  if ((long long)out_size >= 3*bv) mode = 1;                 /* masks as float */
  else if ((long long)out_size >= bv + bv/2) mode = 2;       /* masks as bytes */

  dim3 grid(BPR, NB);
  k_scatter2<<<npb + nob, 256>>>(ptoks, PL, otoks, OL, npb);
  k_pass1<<<grid, 256>>>(logits, pres, rep, temp, out, mode);
  k_select<<<NB, 512>>>(logits, pres, rep, temp, tk, tp);
  k_fill<<<grid, 256>>>(out);
  k_spray<<<NB + npb + nob, 256>>>(out, ptoks, PL, otoks, OL, npb);
}